// round 17
// baseline (speedup 1.0000x reference)
#include <cuda_runtime.h>

// db2 filter constants
#define DL0 (-0.12940952255092145f)
#define DL1 ( 0.22414386804185735f)
#define DL2 ( 0.836516303737469f)
#define DL3 ( 0.48296291314469025f)
#define DH0 (-0.48296291314469025f)
#define DH1 ( 0.836516303737469f)
#define DH2 (-0.22414386804185735f)
#define DH3 (-0.12940952255092145f)
#define RL0 ( 0.48296291314469025f)
#define RL1 ( 0.836516303737469f)
#define RL2 ( 0.22414386804185735f)
#define RL3 (-0.12940952255092145f)
#define RH0 (-0.12940952255092145f)
#define RH1 (-0.22414386804185735f)
#define RH2 ( 0.836516303737469f)
#define RH3 (-0.48296291314469025f)

static constexpr int D        = 512;
static constexpr int WARPS_PB = 4;          // small CTAs
static constexpr int TPB      = WARPS_PB * 32;   // 128
static constexpr int CTAS_PSM = 12;         // regs 40 -> 12 CTAs/SM (48 warps)
static constexpr int NSM      = 148;
static constexpr unsigned FULL = 0xffffffffu;

// 256-bit global load/store (sm_100+)
#define LDG256(r, p)                                                          \
    asm("ld.global.v8.f32 {%0,%1,%2,%3,%4,%5,%6,%7}, [%8];"                   \
        : "=f"((r)[0]), "=f"((r)[1]), "=f"((r)[2]), "=f"((r)[3]),             \
          "=f"((r)[4]), "=f"((r)[5]), "=f"((r)[6]), "=f"((r)[7])              \
        : "l"(p))

#define STG256(p, r)                                                          \
    asm volatile("st.global.v8.f32 [%0], {%1,%2,%3,%4,%5,%6,%7,%8};"          \
        :: "l"(p),                                                            \
           "f"((r)[0]), "f"((r)[1]), "f"((r)[2]), "f"((r)[3]),                \
           "f"((r)[4]), "f"((r)[5]), "f"((r)[6]), "f"((r)[7])                 \
        : "memory")

// 8 outputs from stencil window s[0..11] = x[c-2 .. c+9] and weights w[0..4].
__device__ __forceinline__ void oct_compute(const float* __restrict__ s,
                                            const float* __restrict__ w,
                                            float* __restrict__ z)
{
    float cA[5], cD[5];
#pragma unroll
    for (int i = 0; i < 5; i++) {
        cA[i] = fmaf(s[2*i], DL3, fmaf(s[2*i+1], DL2, fmaf(s[2*i+2], DL1, s[2*i+3] * DL0)));
        cD[i] = fmaf(s[2*i], DH3, fmaf(s[2*i+1], DH2, fmaf(s[2*i+2], DH1, s[2*i+3] * DH0)));
        cD[i] *= w[i];
    }
#pragma unroll
    for (int i = 0; i < 4; i++) {
        float ze = fmaf(RL2, cA[i], fmaf(RL0, cA[i+1], fmaf(RH2, cD[i], RH0 * cD[i+1])));
        float zo = fmaf(RL3, cA[i], fmaf(RL1, cA[i+1], fmaf(RH3, cD[i], RH1 * cD[i+1])));
        z[2*i]   = ze > 0.0f ? ze : 0.01f * ze;
        z[2*i+1] = zo > 0.0f ? zo : 0.01f * zo;
    }
}

// Persistent grid-stride version of the series-best v8 row kernel.
// Exactly one wave of CTAs (148 SM x 12 CTAs); each warp strides over rows.
// Per row: 2x LDG.256 + 8 shuffles + 2x STG.256, all warp-contiguous 1024B
// spans; A<->B seam folded into select + circular shuffle; row edges are
// register fixups (symmetric extension). Across loop iterations the next
// row's loads overlap the previous row's stores (software pipelining for
// free, no prefetch instructions, no wave transitions).
__global__ __launch_bounds__(TPB, CTAS_PSM)
void wavelet_db2_v8p_kernel(const float* __restrict__ x,
                            const float* __restrict__ weight,
                            float* __restrict__ out,
                            int nrows)
{
    const int lane = threadIdx.x & 31;

    // ---- weights: loaded once per warp, reused for every row ----
    const int kA = lane << 2;
    const float4 w4A = __ldg(reinterpret_cast<const float4*>(weight + kA));
    const float  wsA = __ldg(weight + kA + 4);
    const float4 w4B = __ldg(reinterpret_cast<const float4*>(weight + 128 + kA));
    const float  wsB = __ldg(weight + 132 + kA);
    const float wA[5] = {w4A.x, w4A.y, w4A.z, w4A.w, wsA};
    const float wB[5] = {w4B.x, w4B.y, w4B.z, w4B.w, wsB};

    const int warpsTotal = gridDim.x * WARPS_PB;
    const int wid = blockIdx.x * WARPS_PB + (threadIdx.x >> 5);
    const int co = lane << 3;

    const int up = (lane + 31) & 31;    // circular lane-1
    const int dn = (lane + 1) & 31;     // circular lane+1

    for (long long row = wid; row < nrows; row += warpsTotal) {
        const float* __restrict__ rowp = x + row * D;

        float a[8], b[8];
        LDG256(a, rowp + co);          // x[8L .. 8L+7]
        LDG256(b, rowp + 256 + co);    // x[256+8L .. +7]

        // ---- oct A halo ----
        float am2 = __shfl_up_sync(FULL, a[6], 1);      // x[8L-2]
        float am1 = __shfl_up_sync(FULL, a[7], 1);      // x[8L-1]
        if (lane == 0) { am2 = a[1]; am1 = a[0]; }      // symmetric: x[1], x[0]
        const float uA0 = (lane == 0) ? b[0] : a[0];
        const float uA1 = (lane == 0) ? b[1] : a[1];
        const float ap8 = __shfl_sync(FULL, uA0, dn);   // x[8L+8]
        const float ap9 = __shfl_sync(FULL, uA1, dn);   // x[8L+9]

        // ---- oct B halo ----
        const float uB6 = (lane == 31) ? a[6] : b[6];
        const float uB7 = (lane == 31) ? a[7] : b[7];
        const float bm2 = __shfl_sync(FULL, uB6, up);   // x[256+8L-2]
        const float bm1 = __shfl_sync(FULL, uB7, up);   // x[256+8L-1]
        float bp8 = __shfl_down_sync(FULL, b[0], 1);    // x[256+8L+8]
        float bp9 = __shfl_down_sync(FULL, b[1], 1);    // x[256+8L+9]
        if (lane == 31) { bp8 = b[7]; bp9 = b[6]; }     // symmetric: x[511], x[510]

        float* op = out + row * D;

        const float sA[12] = {am2, am1, a[0], a[1], a[2], a[3], a[4], a[5], a[6], a[7], ap8, ap9};
        float zA[8];
        oct_compute(sA, wA, zA);
        STG256(op + co, zA);

        const float sB[12] = {bm2, bm1, b[0], b[1], b[2], b[3], b[4], b[5], b[6], b[7], bp8, bp9};
        float zB[8];
        oct_compute(sB, wB, zB);
        STG256(op + 256 + co, zB);
    }
}

extern "C" void kernel_launch(void* const* d_in, const int* in_sizes, int n_in,
                              void* d_out, int out_size)
{
    const float* x = (const float*)d_in[0];   // (B, 512) fp32
    const float* w = (const float*)d_in[1];   // (2, 257) fp32
    float* out = (float*)d_out;               // (B, 512) fp32

    const int nrows = in_sizes[0] / D;        // 65536
    const int grid  = NSM * CTAS_PSM;         // 1776 — exactly one wave

    wavelet_db2_v8p_kernel<<<grid, TPB>>>(x, w, out, nrows);
}